// round 13
// baseline (speedup 1.0000x reference)
#include <cuda_runtime.h>
#include <cuda_fp16.h>
#include <cstdint>

// FFN: out = (gelu(x @ w_up^T + b_up) @ w_down_q^T) * scale + b_down
// Single-pass fp16 mma.sync m16n8k16 (f32 accum), 8 warps, 64x64 warp tiles
// (cuts LDSM smem traffic 35% vs 4x4 warp grid).

#define M_TOK 16384
#define D_IN  2048
#define D_HID 8192

#define BM 128
#define BN 256
#define NTHREADS 256

#define STAGE 24576            // A 8K @0 | B 16K @8192
#define NS    6
#define SMEM_TOT (NS * STAGE + 2048)

// ---------------- device scratch ----------------
__device__ __half g_x16[(size_t)M_TOK * D_IN];
__device__ __half g_wu[(size_t)D_HID * D_IN];
__device__ __half g_wd[(size_t)D_IN * D_HID];
__device__ __half g_h[(size_t)M_TOK * D_HID];

// ---------------- helpers ----------------
__device__ __forceinline__ uint32_t smem_u32(const void* p) {
    uint32_t a;
    asm("{ .reg .u64 t; cvta.to.shared.u64 t, %1; cvt.u32.u64 %0, t; }" : "=r"(a) : "l"(p));
    return a;
}
__device__ __forceinline__ void cp16(uint32_t dst, const void* src) {
    asm volatile("cp.async.cg.shared.global [%0], [%1], 16;" :: "r"(dst), "l"(src));
}
__device__ __forceinline__ void cp_commit() { asm volatile("cp.async.commit_group;"); }
#define CP_WAIT(N) asm volatile("cp.async.wait_group %0;" :: "n"(N))

__device__ __forceinline__ void ldm_x4(uint32_t* r, uint32_t addr) {
    asm volatile("ldmatrix.sync.aligned.m8n8.x4.shared.b16 {%0,%1,%2,%3}, [%4];"
                 : "=r"(r[0]), "=r"(r[1]), "=r"(r[2]), "=r"(r[3]) : "r"(addr));
}
__device__ __forceinline__ void mma_fp16(float* c, const uint32_t* a, uint32_t b0, uint32_t b1) {
    asm volatile(
        "mma.sync.aligned.m16n8k16.row.col.f32.f16.f16.f32 "
        "{%0,%1,%2,%3}, {%4,%5,%6,%7}, {%8,%9}, {%0,%1,%2,%3};"
        : "+f"(c[0]), "+f"(c[1]), "+f"(c[2]), "+f"(c[3])
        : "r"(a[0]), "r"(a[1]), "r"(a[2]), "r"(a[3]), "r"(b0), "r"(b1));
}

__device__ __forceinline__ float gelu_exact(float v) {
    return 0.5f * v * (1.0f + erff(v * 0.70710678118654752f));
}

// SMEM tile: 32 fp16 (=64B) per row, swizzled: byte = r*64 + ((u ^ ((r>>1)&3))*16)
// Warp layout: 8 warps as 2(M) x 4(N); warp tile 64x64; acc[4][8][4] = 128 regs.

struct MmaCtx {
    uint32_t sb;
    uint32_t dlane;
    uint32_t aoff[2];
    int wm, wn, lane;
};

__device__ __forceinline__ void init_ctx(MmaCtx& cx, const char* smem) {
    const int tid = threadIdx.x;
    cx.lane = tid & 31;
    const int w = tid >> 5;
    cx.wm = w & 1; cx.wn = w >> 1;
    cx.sb = smem_u32(smem);
    const int lr = tid >> 2, lu = tid & 3;
    cx.dlane = lr * 64 + ((lu ^ ((lr >> 1) & 3)) * 16);
    const uint32_t laneSw = ((cx.lane & 15) >> 1) & 3;
#pragma unroll
    for (int s = 0; s < 2; s++)
        cx.aoff[s] = (cx.lane & 15) * 64 + (((2 * s + (cx.lane >> 4)) ^ laneSw) * 16);
}

// One k32 compute step on the stage at byte offset stOff.
__device__ __forceinline__ void mma_step(const MmaCtx& cx, uint32_t stOff,
                                         float acc[4][8][4]) {
    const uint32_t sc = cx.sb + stOff;
#pragma unroll
    for (int s = 0; s < 2; s++) {
        const uint32_t aA = sc + cx.wm * 4096 + cx.aoff[s];
        const uint32_t aB = sc + 8192 + cx.wn * 4096 + cx.aoff[s];
        uint32_t A[4][4], B[4][4];
#pragma unroll
        for (int mt = 0; mt < 4; mt++) ldm_x4(A[mt], aA + mt * 1024);
#pragma unroll
        for (int g = 0; g < 4; g++) ldm_x4(B[g], aB + g * 1024);
#pragma unroll
        for (int g = 0; g < 4; g++)
#pragma unroll
            for (int mt = 0; mt < 4; mt++) {
                mma_fp16(acc[mt][2 * g],     A[mt], B[g][0], B[g][2]);
                mma_fp16(acc[mt][2 * g + 1], A[mt], B[g][1], B[g][3]);
            }
    }
}

// ===========================================================================
// GEMM1: h = gelu(x @ w_up^T + b_up) -> g_h (fp16)
// ===========================================================================
__global__ __launch_bounds__(NTHREADS, 1)
void ffn_g1_mma(const float* __restrict__ bias) {
    extern __shared__ char smem[];
    MmaCtx cx; init_ctx(cx, smem);
    const int tid = threadIdx.x;
    const int rowBase = blockIdx.y * BM;
    const int colBase = blockIdx.x * BN;

    float* bs = (float*)(smem + NS * STAGE);
    bs[tid] = bias[colBase + tid];

    const int lr = tid >> 2, lu = tid & 3;
    const __half* pA  = g_x16 + (size_t)(rowBase + lr) * D_IN + lu * 8;
    const __half* pA2 = pA + (size_t)64 * D_IN;
    const __half* pB  = g_wu  + (size_t)(colBase + lr) * D_IN + lu * 8;

    float acc[4][8][4];
#pragma unroll
    for (int a = 0; a < 4; a++)
#pragma unroll
        for (int b = 0; b < 8; b++)
#pragma unroll
            for (int c = 0; c < 4; c++) acc[a][b][c] = 0.0f;

    auto load_stage = [&](uint32_t stOff, int kk) {
        const uint32_t d = cx.sb + stOff + cx.dlane;
        cp16(d,          pA + kk);
        cp16(d + 4096,   pA2 + kk);
#pragma unroll
        for (int p = 0; p < 4; p++)
            cp16(d + 8192 + p * 4096, pB + kk + (size_t)p * 64 * D_IN);
    };

    const int nIt = D_IN / 32;  // 64
    uint32_t ldOff = 0;
#pragma unroll
    for (int s = 0; s < NS - 1; s++) {
        load_stage(ldOff, s * 32); cp_commit();
        ldOff += STAGE;
    }

    uint32_t cmOff = 0;
    int kNext = (NS - 1) * 32;
    for (int i = 0; i < nIt; i++) {
        CP_WAIT(NS - 2);
        __syncthreads();
        if (kNext < D_IN) {
            load_stage(ldOff, kNext);
            ldOff += STAGE; if (ldOff == NS * STAGE) ldOff = 0;
            kNext += 32;
        }
        cp_commit();
        mma_step(cx, cmOff, acc);
        cmOff += STAGE; if (cmOff == NS * STAGE) cmOff = 0;
    }

    // epilogue: bias + gelu -> fp16 h
    const int mrow0 = rowBase + cx.wm * 64 + (cx.lane >> 2);
#pragma unroll
    for (int mt = 0; mt < 4; mt++) {
#pragma unroll
        for (int j = 0; j < 8; j++) {
            const int nl = cx.wn * 64 + j * 8 + (cx.lane & 3) * 2;
            const float b0 = bs[nl], b1 = bs[nl + 1];
            const float* c = acc[mt][j];
#pragma unroll
            for (int hrow = 0; hrow < 2; hrow++) {
                const float v0 = gelu_exact(c[2 * hrow]     + b0);
                const float v1 = gelu_exact(c[2 * hrow + 1] + b1);
                const uint32_t hp = (uint32_t)__half_as_ushort(__float2half(v0)) |
                                    ((uint32_t)__half_as_ushort(__float2half(v1)) << 16);
                const size_t idx = (size_t)(mrow0 + mt * 16 + hrow * 8) * D_HID + colBase + nl;
                *(uint32_t*)(g_h + idx) = hp;
            }
        }
    }
}

// ===========================================================================
// GEMM2: out = (h @ w_down^T) * scale + b_down
// ===========================================================================
__global__ __launch_bounds__(NTHREADS, 1)
void ffn_g2_mma(const float* __restrict__ scale, const float* __restrict__ bias,
                float* __restrict__ out) {
    extern __shared__ char smem[];
    MmaCtx cx; init_ctx(cx, smem);
    const int tid = threadIdx.x;
    const int rowBase = blockIdx.y * BM;
    const int colBase = blockIdx.x * BN;

    float* ss = (float*)(smem + NS * STAGE);
    float* bs = ss + 256;
    ss[tid] = scale[colBase + tid];
    bs[tid] = bias[colBase + tid];

    const int lr = tid >> 2, lu = tid & 3;
    const __half* pA  = g_h  + (size_t)(rowBase + lr) * D_HID + lu * 8;
    const __half* pA2 = pA + (size_t)64 * D_HID;
    const __half* pB  = g_wd + (size_t)(colBase + lr) * D_HID + lu * 8;

    float acc[4][8][4];
#pragma unroll
    for (int a = 0; a < 4; a++)
#pragma unroll
        for (int b = 0; b < 8; b++)
#pragma unroll
            for (int c = 0; c < 4; c++) acc[a][b][c] = 0.0f;

    auto load_stage = [&](uint32_t stOff, int kk) {
        const uint32_t d = cx.sb + stOff + cx.dlane;
        cp16(d,          pA + kk);
        cp16(d + 4096,   pA2 + kk);
#pragma unroll
        for (int p = 0; p < 4; p++)
            cp16(d + 8192 + p * 4096, pB + kk + (size_t)p * 64 * D_HID);
    };

    const int nIt = D_HID / 32;  // 256
    uint32_t ldOff = 0;
#pragma unroll
    for (int s = 0; s < NS - 1; s++) {
        load_stage(ldOff, s * 32); cp_commit();
        ldOff += STAGE;
    }

    uint32_t cmOff = 0;
    int kNext = (NS - 1) * 32;
    for (int i = 0; i < nIt; i++) {
        CP_WAIT(NS - 2);
        __syncthreads();
        if (kNext < D_HID) {
            load_stage(ldOff, kNext);
            ldOff += STAGE; if (ldOff == NS * STAGE) ldOff = 0;
            kNext += 32;
        }
        cp_commit();
        mma_step(cx, cmOff, acc);
        cmOff += STAGE; if (cmOff == NS * STAGE) cmOff = 0;
    }

    const int mrow0 = rowBase + cx.wm * 64 + (cx.lane >> 2);
#pragma unroll
    for (int mt = 0; mt < 4; mt++) {
#pragma unroll
        for (int j = 0; j < 8; j++) {
            const int nl = cx.wn * 64 + j * 8 + (cx.lane & 3) * 2;
            const float s0 = ss[nl], s1 = ss[nl + 1];
            const float b0 = bs[nl], b1 = bs[nl + 1];
            const float* c = acc[mt][j];
#pragma unroll
            for (int hrow = 0; hrow < 2; hrow++) {
                const float v0 = fmaf(c[2 * hrow],     s0, b0);
                const float v1 = fmaf(c[2 * hrow + 1], s1, b1);
                float* dst = out + (size_t)(mrow0 + mt * 16 + hrow * 8) * D_IN + colBase + nl;
                *(float2*)dst = make_float2(v0, v1);
            }
        }
    }
}

// ===========================================================================
// conversion kernels
// ===========================================================================
__global__ void cvt_f32_h(const float* __restrict__ in, __half* __restrict__ o, int n4) {
    int i = blockIdx.x * blockDim.x + threadIdx.x;
    if (i >= n4) return;
    float4 v = ((const float4*)in)[i];
    uint32_t p0 = (uint32_t)__half_as_ushort(__float2half(v.x)) |
                  ((uint32_t)__half_as_ushort(__float2half(v.y)) << 16);
    uint32_t p1 = (uint32_t)__half_as_ushort(__float2half(v.z)) |
                  ((uint32_t)__half_as_ushort(__float2half(v.w)) << 16);
    ((uint2*)o)[i] = make_uint2(p0, p1);
}

__global__ void cvt_i32_h(const int* __restrict__ q, __half* __restrict__ o, int n4) {
    int i = blockIdx.x * blockDim.x + threadIdx.x;
    if (i >= n4) return;
    int4 v = ((const int4*)q)[i];
    uint32_t p0 = (uint32_t)__half_as_ushort(__float2half((float)v.x)) |
                  ((uint32_t)__half_as_ushort(__float2half((float)v.y)) << 16);
    uint32_t p1 = (uint32_t)__half_as_ushort(__float2half((float)v.z)) |
                  ((uint32_t)__half_as_ushort(__float2half((float)v.w)) << 16);
    ((uint2*)o)[i] = make_uint2(p0, p1);
}

// ===========================================================================
// launch
// ===========================================================================
extern "C" void kernel_launch(void* const* d_in, const int* in_sizes, int n_in,
                              void* d_out, int out_size) {
    const float* x        = (const float*)d_in[0];
    const float* w_up     = (const float*)d_in[1];
    const float* b_up     = (const float*)d_in[2];
    const int*   w_down_q = (const int*)  d_in[3];
    const float* w_scale  = (const float*)d_in[4];
    const float* b_down   = (const float*)d_in[5];
    float*       out      = (float*)d_out;
    (void)in_sizes; (void)n_in; (void)out_size;

    static bool attr_set = false;
    if (!attr_set) {
        cudaFuncSetAttribute(ffn_g1_mma, cudaFuncAttributeMaxDynamicSharedMemorySize, SMEM_TOT);
        cudaFuncSetAttribute(ffn_g2_mma, cudaFuncAttributeMaxDynamicSharedMemorySize, SMEM_TOT);
        attr_set = true;
    }

    __half *x16, *wu, *wd;
    cudaGetSymbolAddress((void**)&x16, g_x16);
    cudaGetSymbolAddress((void**)&wu, g_wu);
    cudaGetSymbolAddress((void**)&wd, g_wd);

    {
        int n4 = (M_TOK * D_IN) / 4;
        cvt_f32_h<<<(n4 + 255) / 256, 256>>>(x, x16, n4);
    }
    {
        int n4 = (D_HID * D_IN) / 4;
        cvt_f32_h<<<(n4 + 255) / 256, 256>>>(w_up, wu, n4);
    }
    {
        int n4 = (D_IN * D_HID) / 4;
        cvt_i32_h<<<(n4 + 255) / 256, 256>>>(w_down_q, wd, n4);
    }

    dim3 block(NTHREADS);
    dim3 grid1(D_HID / BN, M_TOK / BM);  // 32 x 128
    dim3 grid2(D_IN / BN,  M_TOK / BM);  // 8 x 128

    ffn_g1_mma<<<grid1, block, SMEM_TOT>>>(b_up);
    ffn_g2_mma<<<grid2, block, SMEM_TOT>>>(w_scale, b_down, out);
}